// round 1
// baseline (speedup 1.0000x reference)
#include <cuda_runtime.h>
#include <cuda_bf16.h>
#include <math.h>

#define TOKENS   16384
#define DIM      4096
#define NE       64
#define TOPK     8
#define TM       64      // tokens per CTA
#define KT       64      // K chunk
#define NTHREADS 256

// d_out layout (float32):
//   [0, 131072)        top_scores  [16384][8], descending
//   [131072, 262144)   indices     [16384][8], as float
//   [262144, 262208)   counts      [64]

__global__ void zero_counts_kernel(float* __restrict__ out) {
    out[2 * TOKENS * TOPK + threadIdx.x] = 0.0f;
}

__global__ __launch_bounds__(NTHREADS)
void router_kernel(const float* __restrict__ x,
                   const float* __restrict__ W,
                   float* __restrict__ out) {
    __shared__ float xs[TM][KT + 4];   // +4 pad: token groups hit distinct banks
    __shared__ float ws[KT][NE];       // W chunk transposed: ws[k][expert]; reused as scores[64][64]
    __shared__ float hist[NE];

    float acc[4][4] = {};

    const int tid  = threadIdx.x;
    const int tg   = tid >> 4;   // token group 0..15 (4 tokens each)
    const int eg   = tid & 15;   // expert group 0..15 (4 experts each)
    const int tok0 = blockIdx.x * TM;

    if (tid < NE) hist[tid] = 0.0f;

    for (int k0 = 0; k0 < DIM; k0 += KT) {
        __syncthreads();  // previous compute done before overwriting tiles
        // ---- load x tile [64 tokens][64 k] as float4, coalesced ----
        #pragma unroll
        for (int i = 0; i < 4; i++) {
            int p  = tid + NTHREADS * i;  // 0..1023 float4 slots
            int r  = p >> 4;              // token row 0..63
            int c4 = p & 15;              // float4 col 0..15
            float4 v = *(const float4*)&x[(size_t)(tok0 + r) * DIM + k0 + c4 * 4];
            *(float4*)&xs[r][c4 * 4] = v;
        }
        // ---- load W tile transposed: ws[k][e] ----
        {
            int e  = tid & 63;
            int kb = (tid >> 6) * 16;     // 0,16,32,48
            #pragma unroll
            for (int i = 0; i < 4; i++) {
                int kk = kb + i * 4;
                float4 v = *(const float4*)&W[(size_t)e * DIM + k0 + kk];
                ws[kk + 0][e] = v.x;
                ws[kk + 1][e] = v.y;
                ws[kk + 2][e] = v.z;
                ws[kk + 3][e] = v.w;
            }
        }
        __syncthreads();
        // ---- 4x4 register-tile FMA: 64 FMA per 8 LDS.128 ----
        #pragma unroll
        for (int kk = 0; kk < KT; kk += 4) {
            float4 xv[4];
            #pragma unroll
            for (int t = 0; t < 4; t++)
                xv[t] = *(const float4*)&xs[tg * 4 + t][kk];
            #pragma unroll
            for (int i = 0; i < 4; i++) {
                float4 wv = *(const float4*)&ws[kk + i][eg * 4];
                #pragma unroll
                for (int t = 0; t < 4; t++) {
                    float xc = (i == 0) ? xv[t].x : (i == 1) ? xv[t].y
                             : (i == 2) ? xv[t].z : xv[t].w;
                    acc[t][0] = fmaf(xc, wv.x, acc[t][0]);
                    acc[t][1] = fmaf(xc, wv.y, acc[t][1]);
                    acc[t][2] = fmaf(xc, wv.z, acc[t][2]);
                    acc[t][3] = fmaf(xc, wv.w, acc[t][3]);
                }
            }
        }
    }
    __syncthreads();

    // ---- sigmoid -> smem scores (reuse ws as scores[token][expert]) ----
    #pragma unroll
    for (int t = 0; t < 4; t++)
        #pragma unroll
        for (int e = 0; e < 4; e++) {
            float s = 1.0f / (1.0f + expf(-acc[t][e]));
            ws[tg * 4 + t][eg * 4 + e] = s;
        }
    __syncthreads();

    // ---- top-8 per token: warp w owns tokens w*8..w*8+7 ----
    const int wid = tid >> 5, lane = tid & 31;
    for (int tt = 0; tt < 8; tt++) {
        int trow = wid * 8 + tt;
        float s0 = ws[trow][lane];
        float s1 = ws[trow][lane + 32];
        #pragma unroll
        for (int r = 0; r < TOPK; r++) {
            // local candidate, tie-break lower index (matches jax.lax.top_k)
            float bs; int bi;
            if (s0 >= s1) { bs = s0; bi = lane; }
            else          { bs = s1; bi = lane + 32; }
            // butterfly argmax: strictly-greater, or equal with lower index
            #pragma unroll
            for (int off = 16; off > 0; off >>= 1) {
                float os = __shfl_xor_sync(0xffffffffu, bs, off);
                int   oi = __shfl_xor_sync(0xffffffffu, bi, off);
                if (os > bs || (os == bs && oi < bi)) { bs = os; bi = oi; }
            }
            if (lane == 0) {
                size_t gtok = (size_t)(tok0 + trow);
                out[gtok * TOPK + r]                       = bs;
                out[(size_t)TOKENS * TOPK + gtok * TOPK + r] = (float)bi;
                atomicAdd(&hist[bi], 1.0f);
            }
            if      (bi == lane)      s0 = -1.0f;   // scores are in (0,1)
            else if (bi == lane + 32) s1 = -1.0f;
        }
    }
    __syncthreads();
    if (tid < NE) atomicAdd(&out[2 * TOKENS * TOPK + tid], hist[tid]);
}

extern "C" void kernel_launch(void* const* d_in, const int* in_sizes, int n_in,
                              void* d_out, int out_size) {
    const float* x = (const float*)d_in[0];   // [16384, 4096]
    const float* W = (const float*)d_in[1];   // [64, 4096]
    float* out = (float*)d_out;

    zero_counts_kernel<<<1, NE>>>(out);
    router_kernel<<<TOKENS / TM, NTHREADS>>>(x, W, out);
}

// round 13
// speedup vs baseline: 1.9296x; 1.9296x over previous
#include <cuda_runtime.h>
#include <cuda_bf16.h>
#include <cstdint>
#include <math.h>

#define TOKENS 16384
#define DIM    4096
#define NE     64
#define TOPK   8
#define TM     128            // tokens per CTA
#define KC     64             // K per chunk (bf16 row = 128B = SW128 atom)
#define NCH    (DIM / KC)     // 64
#define NT     256

// double-buffered bf16 tiles, each buffer 72KB:
//   A_H/A_M/A_L [128][64]bf16 16KB each | B_H/B_M/B_L [64][64]bf16 8KB each
#define BUF_STRIDE 73728
#define A_H 0
#define A_M 16384
#define A_L 32768
#define B_H 49152
#define B_M 57344
#define B_L 65536
#define HIST_OFF (2 * BUF_STRIDE)
#define SMEM_DYN (HIST_OFF + 256)

#define SW128(o) ((o) ^ (((o) >> 3) & 0x70))

// d_out (float32): [0,131072) top_scores [16384][8] desc; [131072,262144) indices; [262144,262208) counts

__device__ __forceinline__ uint32_t s2u(const void* p) {
    uint32_t a;
    asm("{ .reg .u64 t; cvta.to.shared.u64 t, %1; cvt.u32.u64 %0, t; }" : "=r"(a) : "l"(p));
    return a;
}
__device__ __forceinline__ void ldm4(uint32_t r[4], uint32_t addr) {
    asm volatile("ldmatrix.sync.aligned.m8n8.x4.shared.b16 {%0,%1,%2,%3}, [%4];"
                 : "=r"(r[0]), "=r"(r[1]), "=r"(r[2]), "=r"(r[3]) : "r"(addr));
}
__device__ __forceinline__ void mma16816(float c[4], const uint32_t a[4], const uint32_t b[2]) {
    asm volatile("mma.sync.aligned.m16n8k16.row.col.f32.bf16.bf16.f32 "
                 "{%0,%1,%2,%3}, {%4,%5,%6,%7}, {%8,%9}, {%0,%1,%2,%3};"
                 : "+f"(c[0]), "+f"(c[1]), "+f"(c[2]), "+f"(c[3])
                 : "r"(a[0]), "r"(a[1]), "r"(a[2]), "r"(a[3]), "r"(b[0]), "r"(b[1]));
}
// exact 3-way bf16 split: v = h + m + l, h/m truncated (exact residuals), l = rn(residual2)
__device__ __forceinline__ void split3(float4 v, uint2& h, uint2& m, uint2& l) {
    uint32_t u0 = __float_as_uint(v.x), u1 = __float_as_uint(v.y),
             u2 = __float_as_uint(v.z), u3 = __float_as_uint(v.w);
    h.x = __byte_perm(u0, u1, 0x7632);
    h.y = __byte_perm(u2, u3, 0x7632);
    float r0 = v.x - __uint_as_float(u0 & 0xFFFF0000u);
    float r1 = v.y - __uint_as_float(u1 & 0xFFFF0000u);
    float r2 = v.z - __uint_as_float(u2 & 0xFFFF0000u);
    float r3 = v.w - __uint_as_float(u3 & 0xFFFF0000u);
    uint32_t w0 = __float_as_uint(r0), w1 = __float_as_uint(r1),
             w2 = __float_as_uint(r2), w3 = __float_as_uint(r3);
    m.x = __byte_perm(w0, w1, 0x7632);
    m.y = __byte_perm(w2, w3, 0x7632);
    __nv_bfloat162 l01 = __floats2bfloat162_rn(r0 - __uint_as_float(w0 & 0xFFFF0000u),
                                               r1 - __uint_as_float(w1 & 0xFFFF0000u));
    __nv_bfloat162 l23 = __floats2bfloat162_rn(r2 - __uint_as_float(w2 & 0xFFFF0000u),
                                               r3 - __uint_as_float(w3 & 0xFFFF0000u));
    l.x = *(uint32_t*)&l01;
    l.y = *(uint32_t*)&l23;
}

__global__ void zero_counts_kernel(float* __restrict__ out) {
    out[2 * TOKENS * TOPK + threadIdx.x] = 0.0f;
}

__global__ __launch_bounds__(NT, 1)
void router_mma_kernel(const float* __restrict__ x,
                       const float* __restrict__ W,
                       float* __restrict__ out) {
    extern __shared__ char sm[];
    const int tid = threadIdx.x;
    const int lane = tid & 31, w = tid >> 5;
    const int tok0 = blockIdx.x * TM;
    float* hist = (float*)(sm + HIST_OFF);
    if (tid < NE) hist[tid] = 0.0f;
    const uint32_t sb = s2u(sm);

    // staging coordinates (invariant across chunks)
    uint32_t xoff[8], woff[4];
    #pragma unroll
    for (int i = 0; i < 8; i++) {
        int p = tid + NT * i;
        xoff[i] = SW128((uint32_t)((p >> 4) * 128 + (p & 15) * 8));
    }
    #pragma unroll
    for (int i = 0; i < 4; i++) {
        int p = tid + NT * i;
        woff[i] = SW128((uint32_t)((p >> 4) * 128 + (p & 15) * 8));
    }

    const float* xg = x + (size_t)tok0 * DIM;
    float4 xr[8], wr[4];

    // ---- prologue: chunk 0 load + stage, chunk 1 load ----
    #pragma unroll
    for (int i = 0; i < 8; i++) {
        int p = tid + NT * i;
        xr[i] = *(const float4*)(xg + (size_t)(p >> 4) * DIM + (p & 15) * 4);
    }
    #pragma unroll
    for (int i = 0; i < 4; i++) {
        int p = tid + NT * i;
        wr[i] = *(const float4*)(W + (size_t)(p >> 4) * DIM + (p & 15) * 4);
    }
    {
        char* b0 = sm;
        #pragma unroll
        for (int i = 0; i < 8; i++) {
            uint2 h, m, l; split3(xr[i], h, m, l);
            *(uint2*)(b0 + A_H + xoff[i]) = h;
            *(uint2*)(b0 + A_M + xoff[i]) = m;
            *(uint2*)(b0 + A_L + xoff[i]) = l;
        }
        #pragma unroll
        for (int i = 0; i < 4; i++) {
            uint2 h, m, l; split3(wr[i], h, m, l);
            *(uint2*)(b0 + B_H + woff[i]) = h;
            *(uint2*)(b0 + B_M + woff[i]) = m;
            *(uint2*)(b0 + B_L + woff[i]) = l;
        }
    }
    __syncthreads();
    #pragma unroll
    for (int i = 0; i < 8; i++) {
        int p = tid + NT * i;
        xr[i] = *(const float4*)(xg + (size_t)(p >> 4) * DIM + KC + (p & 15) * 4);
    }
    #pragma unroll
    for (int i = 0; i < 4; i++) {
        int p = tid + NT * i;
        wr[i] = *(const float4*)(W + (size_t)(p >> 4) * DIM + KC + (p & 15) * 4);
    }

    // ---- warp tile: 4x2 grid, warp = (w>>1, w&1): 32 tokens x 32 experts ----
    const int tb = (w >> 1) * 32;
    const int eb = (w & 1) * 32;
    const int aRow = tb + (lane & 15);
    const int aKb  = (lane >> 4) * 16;
    const int bRow = (lane & 7) + ((lane >> 4) << 3);
    const int bKb  = ((lane >> 3) & 1) * 16;

    float acc[2][4][4] = {};      // per-chunk tensor-core accumulator (small scale)
    float master[2][4][4] = {};   // cross-chunk fp32-RN accumulator

    for (int c = 0; c < NCH; c++) {
        const uint32_t A = sb + (uint32_t)(c & 1) * BUF_STRIDE;
        #pragma unroll
        for (int ks = 0; ks < 4; ks++) {
            const int kb0 = ks * 32;
            uint32_t ah[2][4], am[2][4], al[2][4];
            #pragma unroll
            for (int mt = 0; mt < 2; mt++) {
                uint32_t off = SW128((uint32_t)((aRow + mt * 16) * 128 + kb0 + aKb));
                ldm4(ah[mt], A + A_H + off);
                ldm4(am[mt], A + A_M + off);
                ldm4(al[mt], A + A_L + off);
            }
            #pragma unroll
            for (int tg = 0; tg < 2; tg++) {    // n-tile pair: tiles 2tg, 2tg+1
                uint32_t off = SW128((uint32_t)((eb + tg * 16 + bRow) * 128 + kb0 + bKb));
                uint32_t bh[4], bm[4], bl[4];
                ldm4(bh, A + B_H + off);
                ldm4(bm, A + B_M + off);
                ldm4(bl, A + B_L + off);
                #pragma unroll
                for (int hf = 0; hf < 2; hf++) {
                    const int nt = tg * 2 + hf;
                    #pragma unroll
                    for (int mt = 0; mt < 2; mt++) {
                        mma16816(acc[mt][nt], ah[mt], bh + hf * 2);   // hh   (1)
                        mma16816(acc[mt][nt], ah[mt], bm + hf * 2);   // hm   (2^-8)
                        mma16816(acc[mt][nt], am[mt], bh + hf * 2);   // mh   (2^-8)
                        mma16816(acc[mt][nt], am[mt], bm + hf * 2);   // mm   (2^-16)
                        mma16816(acc[mt][nt], ah[mt], bl + hf * 2);   // hl   (2^-16)
                        mma16816(acc[mt][nt], al[mt], bh + hf * 2);   // lh   (2^-16)
                    }
                }
            }
        }
        // ---- drain TC accumulators into RN master accs; keeps the HMMA
        //      accumulation chain short (64 K) and at small magnitude,
        //      bounding the tensor core's non-RN accumulate bias ----
        #pragma unroll
        for (int mt = 0; mt < 2; mt++)
            #pragma unroll
            for (int nt = 0; nt < 4; nt++)
                #pragma unroll
                for (int i = 0; i < 4; i++) {
                    master[mt][nt][i] += acc[mt][nt][i];
                    acc[mt][nt][i] = 0.0f;
                }
        if (c + 1 < NCH) {
            char* bn = sm + (size_t)((c + 1) & 1) * BUF_STRIDE;
            #pragma unroll
            for (int i = 0; i < 8; i++) {
                uint2 h, m, l; split3(xr[i], h, m, l);
                *(uint2*)(bn + A_H + xoff[i]) = h;
                *(uint2*)(bn + A_M + xoff[i]) = m;
                *(uint2*)(bn + A_L + xoff[i]) = l;
            }
            #pragma unroll
            for (int i = 0; i < 4; i++) {
                uint2 h, m, l; split3(wr[i], h, m, l);
                *(uint2*)(bn + B_H + woff[i]) = h;
                *(uint2*)(bn + B_M + woff[i]) = m;
                *(uint2*)(bn + B_L + woff[i]) = l;
            }
        }
        __syncthreads();
        if (c + 2 < NCH) {
            const int k0 = (c + 2) * KC;
            #pragma unroll
            for (int i = 0; i < 8; i++) {
                int p = tid + NT * i;
                xr[i] = *(const float4*)(xg + (size_t)(p >> 4) * DIM + k0 + (p & 15) * 4);
            }
            #pragma unroll
            for (int i = 0; i < 4; i++) {
                int p = tid + NT * i;
                wr[i] = *(const float4*)(W + (size_t)(p >> 4) * DIM + k0 + (p & 15) * 4);
            }
        }
    }

    // ---- sigmoid in fp32 -> smem scores [128][68] ----
    float* sc = (float*)sm;
    #pragma unroll
    for (int mt = 0; mt < 2; mt++)
        #pragma unroll
        for (int nt = 0; nt < 4; nt++) {
            int r0 = tb + mt * 16 + (lane >> 2);
            int c0 = eb + nt * 8 + (lane & 3) * 2;
            sc[r0 * 68 + c0]           = 1.0f / (1.0f + expf(-master[mt][nt][0]));
            sc[r0 * 68 + c0 + 1]       = 1.0f / (1.0f + expf(-master[mt][nt][1]));
            sc[(r0 + 8) * 68 + c0]     = 1.0f / (1.0f + expf(-master[mt][nt][2]));
            sc[(r0 + 8) * 68 + c0 + 1] = 1.0f / (1.0f + expf(-master[mt][nt][3]));
        }
    __syncthreads();

    // ---- per-token top-8 over fp32 sigmoid scores (threads 0..127) ----
    if (tid < TM) {
        float v[64];
        const float4* row = (const float4*)(sc + tid * 68);
        #pragma unroll
        for (int i = 0; i < 16; i++) {
            float4 t = row[i];
            v[4 * i] = t.x; v[4 * i + 1] = t.y; v[4 * i + 2] = t.z; v[4 * i + 3] = t.w;
        }
        const size_t token = (size_t)(tok0 + tid);
        #pragma unroll
        for (int r = 0; r < TOPK; r++) {
            float best = -1.0f; int bi = 0;
            #pragma unroll
            for (int i = 0; i < 64; i++)
                if (v[i] > best) { best = v[i]; bi = i; }   // strict > => lowest index on ties
            out[token * TOPK + r] = best;
            out[(size_t)TOKENS * TOPK + token * TOPK + r] = (float)bi;
            atomicAdd(&hist[bi], 1.0f);
            #pragma unroll
            for (int i = 0; i < 64; i++)
                if (i == bi) v[i] = -1.0f;                  // scores in (0,1)
        }
    }
    __syncthreads();
    if (tid < NE) atomicAdd(&out[2 * TOKENS * TOPK + tid], hist[tid]);
}

extern "C" void kernel_launch(void* const* d_in, const int* in_sizes, int n_in,
                              void* d_out, int out_size) {
    const float* x = (const float*)d_in[0];   // [16384, 4096]
    const float* W = (const float*)d_in[1];   // [64, 4096]
    float* out = (float*)d_out;

    cudaFuncSetAttribute(router_mma_kernel,
                         cudaFuncAttributeMaxDynamicSharedMemorySize, SMEM_DYN);
    zero_counts_kernel<<<1, NE>>>(out);
    router_mma_kernel<<<TOKENS / TM, NT, SMEM_DYN>>>(x, W, out);
}

// round 17
// speedup vs baseline: 2.7235x; 1.4114x over previous
#include <cuda_runtime.h>
#include <cuda_fp16.h>
#include <cstdint>
#include <math.h>

#define TOKENS 16384
#define DIM    4096
#define NE     64
#define TOPK   8
#define TM     128            // tokens per CTA
#define KC     64             // K per chunk (fp16 row = 128B = SW128 atom)
#define NCH    (DIM / KC)     // 64
#define NT     512

// double-buffered fp16 tiles, each buffer 48KB:
//   A_H/A_L [128][64]f16 16KB each | B_H/B_L [64][64]f16 8KB each
#define BUF_STRIDE 49152
#define A_H 0
#define A_L 16384
#define B_H 32768
#define B_L 40960
#define HIST_OFF (2 * BUF_STRIDE)
#define SMEM_DYN (HIST_OFF + 256)

#define SW128(o) ((o) ^ (((o) >> 3) & 0x70))

// d_out (float32): [0,131072) top_scores [16384][8] desc; [131072,262144) indices; [262144,262208) counts

__device__ __forceinline__ uint32_t s2u(const void* p) {
    uint32_t a;
    asm("{ .reg .u64 t; cvta.to.shared.u64 t, %1; cvt.u32.u64 %0, t; }" : "=r"(a) : "l"(p));
    return a;
}
__device__ __forceinline__ void ldm4(uint32_t r[4], uint32_t addr) {
    asm volatile("ldmatrix.sync.aligned.m8n8.x4.shared.b16 {%0,%1,%2,%3}, [%4];"
                 : "=r"(r[0]), "=r"(r[1]), "=r"(r[2]), "=r"(r[3]) : "r"(addr));
}
__device__ __forceinline__ void mma16816(float c[4], const uint32_t a[4], const uint32_t b[2]) {
    asm volatile("mma.sync.aligned.m16n8k16.row.col.f32.f16.f16.f32 "
                 "{%0,%1,%2,%3}, {%4,%5,%6,%7}, {%8,%9}, {%0,%1,%2,%3};"
                 : "+f"(c[0]), "+f"(c[1]), "+f"(c[2]), "+f"(c[3])
                 : "r"(a[0]), "r"(a[1]), "r"(a[2]), "r"(a[3]), "r"(b[0]), "r"(b[1]));
}
// fp16 2-way split: v = h + l + eps, h = rn16(v) (residual v-h exact in fp32),
// l = rn16(v - h). Dropped l*l MMA term ~= 2^-25 |ab| rms -> ~1e-6 logit noise.
__device__ __forceinline__ void split2h(float4 v, uint2& h, uint2& l) {
    __half h0 = __float2half_rn(v.x), h1 = __float2half_rn(v.y),
           h2 = __float2half_rn(v.z), h3 = __float2half_rn(v.w);
    float r0 = v.x - __half2float(h0);
    float r1 = v.y - __half2float(h1);
    float r2 = v.z - __half2float(h2);
    float r3 = v.w - __half2float(h3);
    __half2 hh01 = __halves2half2(h0, h1), hh23 = __halves2half2(h2, h3);
    __half2 ll01 = __floats2half2_rn(r0, r1), ll23 = __floats2half2_rn(r2, r3);
    h.x = *(uint32_t*)&hh01; h.y = *(uint32_t*)&hh23;
    l.x = *(uint32_t*)&ll01; l.y = *(uint32_t*)&ll23;
}

__global__ void zero_counts_kernel(float* __restrict__ out) {
    out[2 * TOKENS * TOPK + threadIdx.x] = 0.0f;
}

__global__ __launch_bounds__(NT, 1)
void router_mma_kernel(const float* __restrict__ x,
                       const float* __restrict__ W,
                       float* __restrict__ out) {
    extern __shared__ char sm[];
    const int tid = threadIdx.x;
    const int lane = tid & 31, w = tid >> 5;
    const int tok0 = blockIdx.x * TM;
    float* hist = (float*)(sm + HIST_OFF);
    if (tid < NE) hist[tid] = 0.0f;
    const uint32_t sb = s2u(sm);

    // staging coordinates (invariant across chunks); 512 threads
    uint32_t xoff[4], woff[2];
    #pragma unroll
    for (int i = 0; i < 4; i++) {
        int p = tid + NT * i;                     // 0..2047 float4 slots of A
        xoff[i] = SW128((uint32_t)((p >> 4) * 128 + (p & 15) * 8));
    }
    #pragma unroll
    for (int i = 0; i < 2; i++) {
        int p = tid + NT * i;                     // 0..1023 float4 slots of B
        woff[i] = SW128((uint32_t)((p >> 4) * 128 + (p & 15) * 8));
    }

    const float* xg = x + (size_t)tok0 * DIM;
    float4 xr[4], wr[2];

    // ---- prologue: chunk 0 load + stage, chunk 1 load ----
    #pragma unroll
    for (int i = 0; i < 4; i++) {
        int p = tid + NT * i;
        xr[i] = *(const float4*)(xg + (size_t)(p >> 4) * DIM + (p & 15) * 4);
    }
    #pragma unroll
    for (int i = 0; i < 2; i++) {
        int p = tid + NT * i;
        wr[i] = *(const float4*)(W + (size_t)(p >> 4) * DIM + (p & 15) * 4);
    }
    {
        char* b0 = sm;
        #pragma unroll
        for (int i = 0; i < 4; i++) {
            uint2 h, l; split2h(xr[i], h, l);
            *(uint2*)(b0 + A_H + xoff[i]) = h;
            *(uint2*)(b0 + A_L + xoff[i]) = l;
        }
        #pragma unroll
        for (int i = 0; i < 2; i++) {
            uint2 h, l; split2h(wr[i], h, l);
            *(uint2*)(b0 + B_H + woff[i]) = h;
            *(uint2*)(b0 + B_L + woff[i]) = l;
        }
    }
    __syncthreads();
    #pragma unroll
    for (int i = 0; i < 4; i++) {
        int p = tid + NT * i;
        xr[i] = *(const float4*)(xg + (size_t)(p >> 4) * DIM + KC + (p & 15) * 4);
    }
    #pragma unroll
    for (int i = 0; i < 2; i++) {
        int p = tid + NT * i;
        wr[i] = *(const float4*)(W + (size_t)(p >> 4) * DIM + KC + (p & 15) * 4);
    }

    // ---- warp tile: 4x4 grid, warp = (w>>2, w&3): 32 tokens x 16 experts ----
    const int tb = (w >> 2) * 32;
    const int eb = (w & 3) * 16;
    const int aRow = tb + (lane & 15);
    const int aKb  = (lane >> 4) * 16;
    const int bRow = (lane & 7) + ((lane >> 4) << 3);
    const int bKb  = ((lane >> 3) & 1) * 16;

    float acc[2][2][4] = {};      // per-chunk tensor-core accumulator (small scale)
    float master[2][2][4] = {};   // cross-chunk fp32-RN accumulator

    for (int c = 0; c < NCH; c++) {
        const uint32_t A = sb + (uint32_t)(c & 1) * BUF_STRIDE;
        #pragma unroll
        for (int ks = 0; ks < 4; ks++) {
            const int kb0 = ks * 32;
            uint32_t ah[2][4], al[2][4];
            #pragma unroll
            for (int mt = 0; mt < 2; mt++) {
                uint32_t off = SW128((uint32_t)((aRow + mt * 16) * 128 + kb0 + aKb));
                ldm4(ah[mt], A + A_H + off);
                ldm4(al[mt], A + A_L + off);
            }
            uint32_t off = SW128((uint32_t)((eb + bRow) * 128 + kb0 + bKb));
            uint32_t bh[4], bl[4];
            ldm4(bh, A + B_H + off);
            ldm4(bl, A + B_L + off);
            #pragma unroll
            for (int hf = 0; hf < 2; hf++) {      // two n8 tiles
                #pragma unroll
                for (int mt = 0; mt < 2; mt++) {
                    mma16816(acc[mt][hf], ah[mt], bh + hf * 2);   // hh   (1)
                    mma16816(acc[mt][hf], ah[mt], bl + hf * 2);   // hl   (2^-12)
                    mma16816(acc[mt][hf], al[mt], bh + hf * 2);   // lh   (2^-12)
                }
            }
        }
        // drain TC accumulators into RN master accs (bounds non-RN TC accumulate bias)
        #pragma unroll
        for (int mt = 0; mt < 2; mt++)
            #pragma unroll
            for (int nt = 0; nt < 2; nt++)
                #pragma unroll
                for (int i = 0; i < 4; i++) {
                    master[mt][nt][i] += acc[mt][nt][i];
                    acc[mt][nt][i] = 0.0f;
                }
        if (c + 1 < NCH) {
            char* bn = sm + (size_t)((c + 1) & 1) * BUF_STRIDE;
            #pragma unroll
            for (int i = 0; i < 4; i++) {
                uint2 h, l; split2h(xr[i], h, l);
                *(uint2*)(bn + A_H + xoff[i]) = h;
                *(uint2*)(bn + A_L + xoff[i]) = l;
            }
            #pragma unroll
            for (int i = 0; i < 2; i++) {
                uint2 h, l; split2h(wr[i], h, l);
                *(uint2*)(bn + B_H + woff[i]) = h;
                *(uint2*)(bn + B_L + woff[i]) = l;
            }
        }
        __syncthreads();
        if (c + 2 < NCH) {
            const int k0 = (c + 2) * KC;
            #pragma unroll
            for (int i = 0; i < 4; i++) {
                int p = tid + NT * i;
                xr[i] = *(const float4*)(xg + (size_t)(p >> 4) * DIM + k0 + (p & 15) * 4);
            }
            #pragma unroll
            for (int i = 0; i < 2; i++) {
                int p = tid + NT * i;
                wr[i] = *(const float4*)(W + (size_t)(p >> 4) * DIM + k0 + (p & 15) * 4);
            }
        }
    }

    // ---- sigmoid in fp32 -> smem scores [128][68] ----
    float* sc = (float*)sm;
    #pragma unroll
    for (int mt = 0; mt < 2; mt++)
        #pragma unroll
        for (int nt = 0; nt < 2; nt++) {
            int r0 = tb + mt * 16 + (lane >> 2);
            int c0 = eb + nt * 8 + (lane & 3) * 2;
            sc[r0 * 68 + c0]           = 1.0f / (1.0f + expf(-master[mt][nt][0]));
            sc[r0 * 68 + c0 + 1]       = 1.0f / (1.0f + expf(-master[mt][nt][1]));
            sc[(r0 + 8) * 68 + c0]     = 1.0f / (1.0f + expf(-master[mt][nt][2]));
            sc[(r0 + 8) * 68 + c0 + 1] = 1.0f / (1.0f + expf(-master[mt][nt][3]));
        }
    __syncthreads();

    // ---- per-token top-8 over fp32 sigmoid scores (threads 0..127) ----
    if (tid < TM) {
        float v[64];
        const float4* row = (const float4*)(sc + tid * 68);
        #pragma unroll
        for (int i = 0; i < 16; i++) {
            float4 t = row[i];
            v[4 * i] = t.x; v[4 * i + 1] = t.y; v[4 * i + 2] = t.z; v[4 * i + 3] = t.w;
        }
        const size_t token = (size_t)(tok0 + tid);
        #pragma unroll
        for (int r = 0; r < TOPK; r++) {
            float best = -1.0f; int bi = 0;
            #pragma unroll
            for (int i = 0; i < 64; i++)
                if (v[i] > best) { best = v[i]; bi = i; }   // strict > => lowest index on ties
            out[token * TOPK + r] = best;
            out[(size_t)TOKENS * TOPK + token * TOPK + r] = (float)bi;
            atomicAdd(&hist[bi], 1.0f);
            #pragma unroll
            for (int i = 0; i < 64; i++)
                if (i == bi) v[i] = -1.0f;                  // scores in (0,1)
        }
    }
    __syncthreads();
    if (tid < NE) atomicAdd(&out[2 * TOKENS * TOPK + tid], hist[tid]);
}

extern "C" void kernel_launch(void* const* d_in, const int* in_sizes, int n_in,
                              void* d_out, int out_size) {
    const float* x = (const float*)d_in[0];   // [16384, 4096]
    const float* W = (const float*)d_in[1];   // [64, 4096]
    float* out = (float*)d_out;

    cudaFuncSetAttribute(router_mma_kernel,
                         cudaFuncAttributeMaxDynamicSharedMemorySize, SMEM_DYN);
    zero_counts_kernel<<<1, NE>>>(out);
    router_mma_kernel<<<TOKENS / TM, NT, SMEM_DYN>>>(x, W, out);
}